// round 15
// baseline (speedup 1.0000x reference)
#include <cuda_runtime.h>
#include <cuda_fp16.h>
#include <math.h>

#define NODES   100000
#define EDGES   1600000
#define TOTE    (EDGES + NODES)
#define INDIM   128
#define HID     64
#define NEG     0.2f

typedef unsigned long long ull;

// ---------------- device scratch ----------------
__device__ float g_h0[NODES * HID];
__device__ float g_h1[NODES * HID];
__device__ uint4 g_xh16[NODES * 8];    // fp16 messages: row = 64 half = 128B
__device__ float g_als[NODES * 4];
__device__ float g_ald[NODES * 4];
__device__ int   g_deg[NODES];
__device__ int   g_incl[NODES];
__device__ int   g_rowptr[NODES + 1];
__device__ int   g_fill[NODES];
__device__ int   g_csr[TOTE];
__device__ int   g_bsum[128];

// ---------------- CSR build ----------------
__global__ void k_hist(const int* __restrict__ dst) {
    int i = blockIdx.x * blockDim.x + threadIdx.x;
    if (i < EDGES) atomicAdd(&g_deg[dst[i]], 1);
}

__global__ void k_scan1() {
    __shared__ int s[1024];
    int tid = threadIdx.x;
    int i = blockIdx.x * 1024 + tid;
    int v = (i < NODES) ? (g_deg[i] + 1) : 0;   // +1 = self-loop
    s[tid] = v;
    __syncthreads();
    #pragma unroll
    for (int off = 1; off < 1024; off <<= 1) {
        int t = (tid >= off) ? s[tid - off] : 0;
        __syncthreads();
        s[tid] += t;
        __syncthreads();
    }
    if (i < NODES) g_incl[i] = s[tid];
    if (tid == 1023) g_bsum[blockIdx.x] = s[1023];
}

// merged scan finalize + self-loop seed; barriers non-divergent
__global__ void k_scan23self(int nb) {
    __shared__ int sincl[128];
    __shared__ int sexcl[128];
    int tid = threadIdx.x;
    if (tid < 128) sincl[tid] = (tid < nb) ? g_bsum[tid] : 0;
    __syncthreads();
    #pragma unroll
    for (int off = 1; off < 128; off <<= 1) {
        int t = 0;
        if (tid < 128 && tid >= off) t = sincl[tid - off];
        __syncthreads();
        if (tid < 128) sincl[tid] += t;
        __syncthreads();
    }
    if (tid < 128) sexcl[tid] = sincl[tid] - ((tid < nb) ? g_bsum[tid] : 0);
    __syncthreads();

    int i = blockIdx.x * blockDim.x + tid;
    if (i == 0) g_rowptr[0] = 0;
    if (i < NODES) {
        g_rowptr[i + 1] = g_incl[i] + sexcl[i >> 10];
        int p = (i == 0) ? 0 : (g_incl[i - 1] + sexcl[(i - 1) >> 10]);
        g_csr[p] = i;          // self-loop first
        g_fill[i] = p + 1;
    }
}

__global__ void k_scatter(const int* __restrict__ src, const int* __restrict__ dst) {
    int e = blockIdx.x * blockDim.x + threadIdx.x;
    if (e < EDGES) {
        int d = dst[e];
        int pos = atomicAdd(&g_fill[d], 1);
        g_csr[pos] = src[e];
    }
}

// ---------------- packed f32x2 helpers ----------------
__device__ __forceinline__ void unpack2(ull v, float& lo, float& hi) {
    unsigned int a, b;
    asm("mov.b64 {%0, %1}, %2;" : "=r"(a), "=r"(b) : "l"(v));
    lo = __uint_as_float(a); hi = __uint_as_float(b);
}
__device__ __forceinline__ void fma2(ull& acc, ull a, ull b) {
    asm("fma.rn.f32x2 %0, %1, %2, %0;" : "+l"(acc) : "l"(a), "l"(b));
}
__device__ __forceinline__ ull dup2(float v) {
    ull r;
    asm("mov.b64 %0, {%1, %1};" : "=l"(r) : "r"(__float_as_uint(v)));
    return r;
}

// ---------------- GEMM: xh = h@W (fp16 store) + attention logits ----------
__global__ void __launch_bounds__(256) k_gemm(
        const float* __restrict__ h, const float* __restrict__ W,
        const float* __restrict__ asrc, const float* __restrict__ adst,
        int din) {
    extern __shared__ float smem[];           // W: din*64 | staging: 8 warps * 8*din
    float* Ws = smem;
    int tid = threadIdx.x;
    int lane = tid & 31;
    int warp = tid >> 5;
    float* Hs = smem + din * 64 + warp * 8 * din;

    for (int i = tid; i < din * 16; i += blockDim.x)
        ((float4*)Ws)[i] = ((const float4*)W)[i];
    __syncthreads();

    float as0 = asrc[2 * lane], as1 = asrc[2 * lane + 1];
    float ad0 = adst[2 * lane], ad1 = adst[2 * lane + 1];

    int gwarp = (blockIdx.x * blockDim.x + tid) >> 5;
    int nwarps = (gridDim.x * blockDim.x) >> 5;
    const int ngroups = NODES >> 3;           // 12500, exact

    for (int g = gwarp; g < ngroups; g += nwarps) {
        int n0 = g * 8;
        {
            const float4* hsrc = (const float4*)&h[n0 * din];
            int nf4 = 2 * din;
            for (int i = lane; i < nf4; i += 32)
                ((float4*)Hs)[i] = hsrc[i];
        }
        __syncwarp();

        ull acc[8] = {0ull,0ull,0ull,0ull,0ull,0ull,0ull,0ull};

        for (int k0 = 0; k0 < din; k0 += 4) {
            float4 h4[8];
            #pragma unroll
            for (int i = 0; i < 8; i++)
                h4[i] = *(const float4*)&Hs[i * din + k0];
            #pragma unroll
            for (int j = 0; j < 4; j++) {
                ull w2 = *(const ull*)&Ws[(k0 + j) * HID + 2 * lane];
                #pragma unroll
                for (int i = 0; i < 8; i++)
                    fma2(acc[i], dup2(((const float*)&h4[i])[j]), w2);
            }
        }
        __syncwarp();

        #pragma unroll
        for (int i = 0; i < 8; i++) {
            int nd = n0 + i;
            float ax, ay;
            unpack2(acc[i], ax, ay);
            ((__half2*)g_xh16)[nd * 32 + lane] = __floats2half2_rn(ax, ay);
            float ts = ax * as0 + ay * as1;
            float td = ax * ad0 + ay * ad1;
            ts += __shfl_xor_sync(0xffffffffu, ts, 1);
            ts += __shfl_xor_sync(0xffffffffu, ts, 2);
            ts += __shfl_xor_sync(0xffffffffu, ts, 4);
            td += __shfl_xor_sync(0xffffffffu, td, 1);
            td += __shfl_xor_sync(0xffffffffu, td, 2);
            td += __shfl_xor_sync(0xffffffffu, td, 4);
            if ((lane & 7) == 0) {
                g_als[nd * 4 + (lane >> 3)] = ts;
                g_ald[nd * 4 + (lane >> 3)] = td;
            }
        }
    }
}

// ---------------- edge-parallel softmax-aggregation, 2 nodes/warp --------
// lane = half*16 + eslot*8 + cl. Inner loop batches 8 edges per eslot
// (16 edges per node-half iteration = whole average node in one L2 trip).
__device__ __forceinline__ void accum16(uint4 x, float p, float4& a0, float4& a1) {
    float2 f;
    f = __half22float2(*(__half2*)&x.x); a0.x = fmaf(p, f.x, a0.x); a0.y = fmaf(p, f.y, a0.y);
    f = __half22float2(*(__half2*)&x.y); a0.z = fmaf(p, f.x, a0.z); a0.w = fmaf(p, f.y, a0.w);
    f = __half22float2(*(__half2*)&x.z); a1.x = fmaf(p, f.x, a1.x); a1.y = fmaf(p, f.y, a1.y);
    f = __half22float2(*(__half2*)&x.w); a1.z = fmaf(p, f.x, a1.z); a1.w = fmaf(p, f.y, a1.w);
}

template<bool FINAL>
__global__ void __launch_bounds__(256) k_agg(
                      const int* __restrict__ rowptr, const int* __restrict__ csr,
                      const float* __restrict__ als, const float* __restrict__ ald,
                      const uint4* __restrict__ xh,
                      const float* __restrict__ b, float* __restrict__ hout,
                      const float* __restrict__ ow, const float* __restrict__ ob,
                      float* __restrict__ out) {
    int tid = threadIdx.x;
    int lane = tid & 31;
    int half = lane >> 4;
    int l16 = lane & 15;
    int eslot = l16 >> 3;
    int cl = l16 & 7;
    int head = cl >> 1;
    int gwarp = (blockIdx.x * blockDim.x + tid) >> 5;
    int nwarps = (gridDim.x * blockDim.x) >> 5;

    float4 bias0 = *(const float4*)&b[cl * 8];
    float4 bias1 = *(const float4*)&b[cl * 8 + 4];
    float4 ow0, ow1;
    if (FINAL) {
        ow0 = *(const float4*)&ow[cl * 8];
        ow1 = *(const float4*)&ow[cl * 8 + 4];
    }

    const int npairs = NODES >> 1;   // 50000, exact
    for (int pr = gwarp; pr < npairs; pr += nwarps) {
        int n = 2 * pr + half;
        int beg = rowptr[n];
        int end = rowptr[n + 1];
        float ad_h = ald[n * 4 + head];

        float4 a0 = make_float4(0.f, 0.f, 0.f, 0.f);
        float4 a1 = make_float4(0.f, 0.f, 0.f, 0.f);
        float z = 0.f;

        for (int i0 = beg + eslot; i0 < end; i0 += 16) {
            int s[8];
            int s0 = csr[i0];
            s[0] = s0;
            #pragma unroll
            for (int j = 1; j < 8; j++) {
                int ii = i0 + 2 * j;
                s[j] = (ii < end) ? csr[ii] : s0;
            }
            // all 8 attention-logit gathers issued together
            float e[8];
            #pragma unroll
            for (int j = 0; j < 8; j++) e[j] = als[s[j] * 4 + head];
            // all 8 message gathers issued together (one 128B line each)
            uint4 xv[8];
            #pragma unroll
            for (int j = 0; j < 8; j++) xv[j] = xh[s[j] * 8 + cl];

            #pragma unroll
            for (int j = 0; j < 8; j++) {
                float ej = e[j] + ad_h;
                ej = (ej > 0.f) ? ej : NEG * ej;
                float p = __expf(ej);
                if (j > 0 && (i0 + 2 * j) >= end) p = 0.f;
                z += p;
                accum16(xv[j], p, a0, a1);
            }
        }

        // fold the 2 edge-slots (lane bit 3); node halves independent
        z    += __shfl_xor_sync(0xffffffffu, z, 8);
        a0.x += __shfl_xor_sync(0xffffffffu, a0.x, 8);
        a0.y += __shfl_xor_sync(0xffffffffu, a0.y, 8);
        a0.z += __shfl_xor_sync(0xffffffffu, a0.z, 8);
        a0.w += __shfl_xor_sync(0xffffffffu, a0.w, 8);
        a1.x += __shfl_xor_sync(0xffffffffu, a1.x, 8);
        a1.y += __shfl_xor_sync(0xffffffffu, a1.y, 8);
        a1.z += __shfl_xor_sync(0xffffffffu, a1.z, 8);
        a1.w += __shfl_xor_sync(0xffffffffu, a1.w, 8);

        if (eslot == 0) {   // active lanes: 0-7 (node 2p) and 16-23 (node 2p+1)
            float inv = 1.f / (z + 1e-16f);
            float4 o0, o1;
            o0.x = fmaxf(fmaf(a0.x, inv, bias0.x), 0.f);
            o0.y = fmaxf(fmaf(a0.y, inv, bias0.y), 0.f);
            o0.z = fmaxf(fmaf(a0.z, inv, bias0.z), 0.f);
            o0.w = fmaxf(fmaf(a0.w, inv, bias0.w), 0.f);
            o1.x = fmaxf(fmaf(a1.x, inv, bias1.x), 0.f);
            o1.y = fmaxf(fmaf(a1.y, inv, bias1.y), 0.f);
            o1.z = fmaxf(fmaf(a1.z, inv, bias1.z), 0.f);
            o1.w = fmaxf(fmaf(a1.w, inv, bias1.w), 0.f);
            if (FINAL) {
                float t = o0.x * ow0.x + o0.y * ow0.y + o0.z * ow0.z + o0.w * ow0.w
                        + o1.x * ow1.x + o1.y * ow1.y + o1.z * ow1.z + o1.w * ow1.w;
                t += __shfl_xor_sync(0x00ff00ffu, t, 1);
                t += __shfl_xor_sync(0x00ff00ffu, t, 2);
                t += __shfl_xor_sync(0x00ff00ffu, t, 4);
                if (cl == 0) out[n] = t + ob[0];
            } else {
                float* orow = &hout[n * HID + cl * 8];
                *(float4*)orow = o0;
                *(float4*)(orow + 4) = o1;
            }
        }
    }
}

// ---------------- host ----------------
extern "C" void kernel_launch(void* const* d_in, const int* in_sizes, int n_in,
                              void* d_out, int out_size) {
    const float* x   = (const float*)d_in[0];
    const int*   ei  = (const int*)d_in[1];
    const int*   src = ei;
    const int*   dst = ei + EDGES;
    const float* w[3]    = { (const float*)d_in[2], (const float*)d_in[6],  (const float*)d_in[10] };
    const float* asrc[3] = { (const float*)d_in[3], (const float*)d_in[7],  (const float*)d_in[11] };
    const float* adst[3] = { (const float*)d_in[4], (const float*)d_in[8],  (const float*)d_in[12] };
    const float* bb[3]   = { (const float*)d_in[5], (const float*)d_in[9],  (const float*)d_in[13] };
    const float* out_w = (const float*)d_in[14];
    const float* out_b = (const float*)d_in[15];
    float* out = (float*)d_out;

    float *h0, *h1, *alsp, *aldp; int *degp, *rowp, *csrp; uint4* xhp;
    cudaGetSymbolAddress((void**)&h0, g_h0);
    cudaGetSymbolAddress((void**)&h1, g_h1);
    cudaGetSymbolAddress((void**)&degp, g_deg);
    cudaGetSymbolAddress((void**)&rowp, g_rowptr);
    cudaGetSymbolAddress((void**)&csrp, g_csr);
    cudaGetSymbolAddress((void**)&alsp, g_als);
    cudaGetSymbolAddress((void**)&aldp, g_ald);
    cudaGetSymbolAddress((void**)&xhp, g_xh16);

    const int smem0 = (INDIM * 64 + 8 * 8 * INDIM) * sizeof(float);   // 64KB
    const int smem12 = (HID * 64 + 8 * 8 * HID) * sizeof(float);      // 32KB

    static cudaStream_t s2;
    static cudaEvent_t evFork, evJoin;
    static int init_done = 0;
    if (!init_done) {
        cudaFuncSetAttribute(k_gemm, cudaFuncAttributeMaxDynamicSharedMemorySize, smem0);
        cudaStreamCreateWithFlags(&s2, cudaStreamNonBlocking);
        cudaEventCreateWithFlags(&evFork, cudaEventDisableTiming);
        cudaEventCreateWithFlags(&evJoin, cudaEventDisableTiming);
        init_done = 1;
    }

    // fork: layer-0 GEMM runs concurrently with the CSR build
    cudaEventRecord(evFork, 0);
    cudaStreamWaitEvent(s2, evFork, 0);
    k_gemm<<<1563, 256, smem0, s2>>>(x, w[0], asrc[0], adst[0], INDIM);
    cudaEventRecord(evJoin, s2);

    // CSR build on the main stream
    cudaMemsetAsync(degp, 0, NODES * sizeof(int));
    k_hist<<<(EDGES + 255) / 256, 256>>>(dst);
    k_scan1<<<(NODES + 1023) / 1024, 1024>>>();
    k_scan23self<<<(NODES + 255) / 256, 256>>>((NODES + 1023) / 1024);
    k_scatter<<<(EDGES + 255) / 256, 256>>>(src, dst);

    // join before aggregation
    cudaStreamWaitEvent(0, evJoin, 0);

    k_agg<false><<<2048, 256>>>(rowp, csrp, alsp, aldp, xhp, bb[0], h0,
                                nullptr, nullptr, nullptr);
    k_gemm<<<1563, 256, smem12>>>(h0, w[1], asrc[1], adst[1], HID);
    k_agg<false><<<2048, 256>>>(rowp, csrp, alsp, aldp, xhp, bb[1], h1,
                                nullptr, nullptr, nullptr);
    k_gemm<<<1563, 256, smem12>>>(h1, w[2], asrc[2], adst[2], HID);
    k_agg<true><<<2048, 256>>>(rowp, csrp, alsp, aldp, xhp, bb[2], nullptr,
                               out_w, out_b, out);
}